// round 13
// baseline (speedup 1.0000x reference)
#include <cuda_runtime.h>
#include <cuda_bf16.h>

// ST-BIF multi-step neuron, T=4 timesteps. HBM-bound streaming kernel.
// Persistent grid-stride variant: exactly one wave (148 SMs x 8 CTAs),
// each CTA loops over ~10 tiles -> no wave transitions, cross-iteration
// load overlap. Body identical to the best-measured R7 configuration.

#define POS_MAX 15.0f
#define NEG_MIN 0.0f
#define TSTEPS  4

__device__ __forceinline__ float bif_step(float& v, float& tc, float xv, float vth) {
    float H = v + xv;
    float spike;
    if (H >= vth && tc < POS_MAX)      spike = 1.0f;
    else if (H < 0.0f && tc > NEG_MIN) spike = -1.0f;
    else                               spike = 0.0f;
    v  = H - spike * vth;
    tc = tc + spike;
    return spike * vth;
}

__global__ void __launch_bounds__(256, 8)
st_bif_ms_kernel(const float* __restrict__ x,
                 const float* __restrict__ qth_ptr,
                 float* __restrict__ out,
                 int stepN)  // elements per timestep (B*L*D)
{
    const float vth = __ldg(qth_ptr);
    const int stride = gridDim.x * blockDim.x * 4;   // floats per grid pass

    for (int idx = (blockIdx.x * blockDim.x + threadIdx.x) * 4;
         idx < stepN; idx += stride) {

        // Front-batch all 4 timestep loads (MLP=4), streaming / evict-first.
        float4 xs0 = __ldcs(reinterpret_cast<const float4*>(x + idx));
        float4 xs1 = __ldcs(reinterpret_cast<const float4*>(x + idx + (size_t)stepN));
        float4 xs2 = __ldcs(reinterpret_cast<const float4*>(x + idx + (size_t)2 * stepN));
        float4 xs3 = __ldcs(reinterpret_cast<const float4*>(x + idx + (size_t)3 * stepN));

        float v[4], tc[4];
        #pragma unroll
        for (int j = 0; j < 4; j++) { v[j] = 0.5f * vth; tc[j] = 0.0f; }

        float4 o;

        // t = 0
        o.x = bif_step(v[0], tc[0], xs0.x, vth);
        o.y = bif_step(v[1], tc[1], xs0.y, vth);
        o.z = bif_step(v[2], tc[2], xs0.z, vth);
        o.w = bif_step(v[3], tc[3], xs0.w, vth);
        __stcs(reinterpret_cast<float4*>(out + idx), o);

        // t = 1
        o.x = bif_step(v[0], tc[0], xs1.x, vth);
        o.y = bif_step(v[1], tc[1], xs1.y, vth);
        o.z = bif_step(v[2], tc[2], xs1.z, vth);
        o.w = bif_step(v[3], tc[3], xs1.w, vth);
        __stcs(reinterpret_cast<float4*>(out + idx + (size_t)stepN), o);

        // t = 2
        o.x = bif_step(v[0], tc[0], xs2.x, vth);
        o.y = bif_step(v[1], tc[1], xs2.y, vth);
        o.z = bif_step(v[2], tc[2], xs2.z, vth);
        o.w = bif_step(v[3], tc[3], xs2.w, vth);
        __stcs(reinterpret_cast<float4*>(out + idx + (size_t)2 * stepN), o);

        // t = 3
        o.x = bif_step(v[0], tc[0], xs3.x, vth);
        o.y = bif_step(v[1], tc[1], xs3.y, vth);
        o.z = bif_step(v[2], tc[2], xs3.z, vth);
        o.w = bif_step(v[3], tc[3], xs3.w, vth);
        __stcs(reinterpret_cast<float4*>(out + idx + (size_t)3 * stepN), o);
    }
}

extern "C" void kernel_launch(void* const* d_in, const int* in_sizes, int n_in,
                              void* d_out, int out_size) {
    const float* x   = (const float*)d_in[0];   // [T*B, L, D] fp32
    const float* qth = (const float*)d_in[1];   // scalar fp32
    float* out = (float*)d_out;

    int total = in_sizes[0];         // T*B*L*D = 50,331,648
    int stepN = total / TSTEPS;      // B*L*D   = 12,582,912 (divisible by 4)

    // One full wave: 148 SMs x 8 CTAs/SM (regs=32/256thr -> 8 resident)
    int blocks = 148 * 8;            // 1184 persistent CTAs
    int tpb = 256;
    st_bif_ms_kernel<<<blocks, tpb>>>(x, qth, out, stepN);
}

// round 14
// speedup vs baseline: 1.1309x; 1.1309x over previous
#include <cuda_runtime.h>
#include <cuda_bf16.h>

// ST-BIF multi-step neuron, T=4 timesteps. HBM-bound streaming kernel at the
// measured DRAM read/write-mix ceiling (~6.1-6.2 TB/s, 77% of 8 TB/s spec).
// Best-measured configuration across 6 structural variants (R6-R12):
//  - flat grid, 32-bit thread indexing (64-bit arith regressed, R9)
//  - 1 float4 per thread, 4 front-batched LDG.128 (MLP=4)
//  - per-timestep stores, small live range (regs=32, occ ~83%)
//  - evict-first (.cs) hints both directions
// Neutral variants: MLP=8 (R8), 256-bit accesses (R11). Regressions:
// 64-bit indexing (R9), persistent grid (R12).

#define POS_MAX 15.0f
#define NEG_MIN 0.0f
#define TSTEPS  4

__device__ __forceinline__ float bif_step(float& v, float& tc, float xv, float vth) {
    float H = v + xv;
    float spike;
    if (H >= vth && tc < POS_MAX)      spike = 1.0f;
    else if (H < 0.0f && tc > NEG_MIN) spike = -1.0f;
    else                               spike = 0.0f;
    v  = H - spike * vth;
    tc = tc + spike;
    return spike * vth;
}

__global__ void __launch_bounds__(256, 8)
st_bif_ms_kernel(const float* __restrict__ x,
                 const float* __restrict__ qth_ptr,
                 float* __restrict__ out,
                 int stepN)  // elements per timestep (B*L*D)
{
    int idx = (blockIdx.x * blockDim.x + threadIdx.x) * 4;
    if (idx >= stepN) return;

    const float vth = __ldg(qth_ptr);

    // Front-batch all 4 timestep loads (MLP=4), streaming / evict-first.
    const float4* p0 = reinterpret_cast<const float4*>(x + idx);
    const float4* p1 = reinterpret_cast<const float4*>(x + idx + (size_t)stepN);
    const float4* p2 = reinterpret_cast<const float4*>(x + idx + (size_t)2 * stepN);
    const float4* p3 = reinterpret_cast<const float4*>(x + idx + (size_t)3 * stepN);
    float4 xs0 = __ldcs(p0);
    float4 xs1 = __ldcs(p1);
    float4 xs2 = __ldcs(p2);
    float4 xs3 = __ldcs(p3);

    float v[4], tc[4];
    #pragma unroll
    for (int j = 0; j < 4; j++) { v[j] = 0.5f * vth; tc[j] = 0.0f; }

    float4 o;

    // t = 0: compute then store immediately (shrinks live range -> fewer regs)
    o.x = bif_step(v[0], tc[0], xs0.x, vth);
    o.y = bif_step(v[1], tc[1], xs0.y, vth);
    o.z = bif_step(v[2], tc[2], xs0.z, vth);
    o.w = bif_step(v[3], tc[3], xs0.w, vth);
    __stcs(reinterpret_cast<float4*>(out + idx), o);

    // t = 1
    o.x = bif_step(v[0], tc[0], xs1.x, vth);
    o.y = bif_step(v[1], tc[1], xs1.y, vth);
    o.z = bif_step(v[2], tc[2], xs1.z, vth);
    o.w = bif_step(v[3], tc[3], xs1.w, vth);
    __stcs(reinterpret_cast<float4*>(out + idx + (size_t)stepN), o);

    // t = 2
    o.x = bif_step(v[0], tc[0], xs2.x, vth);
    o.y = bif_step(v[1], tc[1], xs2.y, vth);
    o.z = bif_step(v[2], tc[2], xs2.z, vth);
    o.w = bif_step(v[3], tc[3], xs2.w, vth);
    __stcs(reinterpret_cast<float4*>(out + idx + (size_t)2 * stepN), o);

    // t = 3
    o.x = bif_step(v[0], tc[0], xs3.x, vth);
    o.y = bif_step(v[1], tc[1], xs3.y, vth);
    o.z = bif_step(v[2], tc[2], xs3.z, vth);
    o.w = bif_step(v[3], tc[3], xs3.w, vth);
    __stcs(reinterpret_cast<float4*>(out + idx + (size_t)3 * stepN), o);
}

extern "C" void kernel_launch(void* const* d_in, const int* in_sizes, int n_in,
                              void* d_out, int out_size) {
    const float* x   = (const float*)d_in[0];   // [T*B, L, D] fp32
    const float* qth = (const float*)d_in[1];   // scalar fp32
    float* out = (float*)d_out;

    int total = in_sizes[0];         // T*B*L*D = 50,331,648
    int stepN = total / TSTEPS;      // B*L*D   = 12,582,912 (divisible by 4)

    int threads = stepN / 4;         // one thread per float4 per timestep
    int tpb = 256;
    int blocks = (threads + tpb - 1) / tpb;   // 12288
    st_bif_ms_kernel<<<blocks, tpb>>>(x, qth, out, stepN);
}

// round 15
// speedup vs baseline: 1.1401x; 1.0081x over previous
#include <cuda_runtime.h>
#include <cuda_bf16.h>

// ST-BIF multi-step neuron, T=4 timesteps. HBM-bound streaming kernel at the
// measured DRAM read/write-mix ceiling (~6.1-6.2 TB/s, ~77% of 8 TB/s spec).
// Configuration = best-measured R7 body; this round: tpb 256->512 (same
// 64 warps/SM, half the CTA boundaries) as a final noise-level polish.
//  - flat grid, 32-bit thread indexing (64-bit arith regressed, R9)
//  - 1 float4 per thread, 4 front-batched LDG.128 (MLP=4)
//  - per-timestep stores, small live range (regs=32)
//  - evict-first (.cs) hints both directions
// Neutral: MLP=8 (R8), 256-bit accesses (R11). Regressions: 64-bit
// indexing (R9), persistent grid (R12).

#define POS_MAX 15.0f
#define NEG_MIN 0.0f
#define TSTEPS  4

__device__ __forceinline__ float bif_step(float& v, float& tc, float xv, float vth) {
    float H = v + xv;
    float spike;
    if (H >= vth && tc < POS_MAX)      spike = 1.0f;
    else if (H < 0.0f && tc > NEG_MIN) spike = -1.0f;
    else                               spike = 0.0f;
    v  = H - spike * vth;
    tc = tc + spike;
    return spike * vth;
}

__global__ void __launch_bounds__(512, 4)
st_bif_ms_kernel(const float* __restrict__ x,
                 const float* __restrict__ qth_ptr,
                 float* __restrict__ out,
                 int stepN)  // elements per timestep (B*L*D)
{
    int idx = (blockIdx.x * blockDim.x + threadIdx.x) * 4;
    if (idx >= stepN) return;

    const float vth = __ldg(qth_ptr);

    // Front-batch all 4 timestep loads (MLP=4), streaming / evict-first.
    const float4* p0 = reinterpret_cast<const float4*>(x + idx);
    const float4* p1 = reinterpret_cast<const float4*>(x + idx + (size_t)stepN);
    const float4* p2 = reinterpret_cast<const float4*>(x + idx + (size_t)2 * stepN);
    const float4* p3 = reinterpret_cast<const float4*>(x + idx + (size_t)3 * stepN);
    float4 xs0 = __ldcs(p0);
    float4 xs1 = __ldcs(p1);
    float4 xs2 = __ldcs(p2);
    float4 xs3 = __ldcs(p3);

    float v[4], tc[4];
    #pragma unroll
    for (int j = 0; j < 4; j++) { v[j] = 0.5f * vth; tc[j] = 0.0f; }

    float4 o;

    // t = 0: compute then store immediately (shrinks live range -> fewer regs)
    o.x = bif_step(v[0], tc[0], xs0.x, vth);
    o.y = bif_step(v[1], tc[1], xs0.y, vth);
    o.z = bif_step(v[2], tc[2], xs0.z, vth);
    o.w = bif_step(v[3], tc[3], xs0.w, vth);
    __stcs(reinterpret_cast<float4*>(out + idx), o);

    // t = 1
    o.x = bif_step(v[0], tc[0], xs1.x, vth);
    o.y = bif_step(v[1], tc[1], xs1.y, vth);
    o.z = bif_step(v[2], tc[2], xs1.z, vth);
    o.w = bif_step(v[3], tc[3], xs1.w, vth);
    __stcs(reinterpret_cast<float4*>(out + idx + (size_t)stepN), o);

    // t = 2
    o.x = bif_step(v[0], tc[0], xs2.x, vth);
    o.y = bif_step(v[1], tc[1], xs2.y, vth);
    o.z = bif_step(v[2], tc[2], xs2.z, vth);
    o.w = bif_step(v[3], tc[3], xs2.w, vth);
    __stcs(reinterpret_cast<float4*>(out + idx + (size_t)2 * stepN), o);

    // t = 3
    o.x = bif_step(v[0], tc[0], xs3.x, vth);
    o.y = bif_step(v[1], tc[1], xs3.y, vth);
    o.z = bif_step(v[2], tc[2], xs3.z, vth);
    o.w = bif_step(v[3], tc[3], xs3.w, vth);
    __stcs(reinterpret_cast<float4*>(out + idx + (size_t)3 * stepN), o);
}

extern "C" void kernel_launch(void* const* d_in, const int* in_sizes, int n_in,
                              void* d_out, int out_size) {
    const float* x   = (const float*)d_in[0];   // [T*B, L, D] fp32
    const float* qth = (const float*)d_in[1];   // scalar fp32
    float* out = (float*)d_out;

    int total = in_sizes[0];         // T*B*L*D = 50,331,648
    int stepN = total / TSTEPS;      // B*L*D   = 12,582,912 (divisible by 4)

    int threads = stepN / 4;         // one thread per float4 per timestep
    int tpb = 512;
    int blocks = (threads + tpb - 1) / tpb;   // 6144
    st_bif_ms_kernel<<<blocks, tpb>>>(x, qth, out, stepN);
}